// round 13
// baseline (speedup 1.0000x reference)
#include <cuda_runtime.h>
#include <cub/cub.cuh>

#define NPIX   9216     // 96*96
#define NANCH  82944    // NPIX*9
#define PRE_N  6000
#define POS_N  300
#define NWORDS 94       // ceil(6000/64)
#define NTILE  2304     // 48*48 winograd 2x2 tiles

// ---------------- scratch (static device memory; no allocation) ----------------
__device__ float g_V[16*1024*NTILE];        // winograd input  [k16][ci][tile]
__device__ float g_U[16*1024*512];          // winograd weight [k16][ci][oc]
__device__ float g_M[16*512*NTILE];         // winograd product [k16][oc][tile]
__device__ float g_h[512*NPIX];             // relu(conv3x3) output [oc][pix]
__device__ float g_cls[18*NPIX];            // cls logits [ch][pix] (for gather_valid)
__device__ float g_prop[NANCH*4];           // unclipped proposals
__device__ float g_bbox[NANCH*4];           // clipped boxes
__device__ unsigned g_keys32[NANCH];
__device__ int      g_vals32[NANCH];
__device__ unsigned g_keys32_s[NANCH];
__device__ int      g_vals32_s[NANCH];
__device__ unsigned char g_cub_temp[8<<20];

// ---------------- packed f32x2 helpers ----------------
__device__ __forceinline__ void ffma2(unsigned long long &d,
                                      unsigned long long a,
                                      unsigned long long b) {
    asm("fma.rn.f32x2 %0, %1, %2, %0;" : "+l"(d) : "l"(a), "l"(b));
}
__device__ __forceinline__ float f2_lo(unsigned long long v) {
    return __uint_as_float((unsigned)(v & 0xffffffffull));
}
__device__ __forceinline__ float f2_hi(unsigned long long v) {
    return __uint_as_float((unsigned)(v >> 32));
}

__global__ void noop_kernel() {}

// ---------------- merged prep: input transform (blocks 0..9215) + weight transform ----------------
__global__ void __launch_bounds__(256) prep_kernel(const float* __restrict__ x,
                                                   const float* __restrict__ wsrc) {
    if (blockIdx.x < 9216) {
        const int ci = blockIdx.x / 9;
        const int t  = (blockIdx.x % 9) * 256 + threadIdx.x;   // 0..2303
        const int ty = t / 48, tx = t % 48;
        const int r0 = 2*ty - 1, c0 = 2*tx - 1;
        const float* xp = x + (size_t)ci * NPIX;

        float d[4][4];
#pragma unroll
        for (int a = 0; a < 4; a++) {
            const int rr = r0 + a;
            const bool rok = (unsigned)rr < 96u;
#pragma unroll
            for (int b = 0; b < 4; b++) {
                const int cc = c0 + b;
                d[a][b] = (rok && (unsigned)cc < 96u) ? xp[rr*96 + cc] : 0.f;
            }
        }
        float w[4][4];
#pragma unroll
        for (int j = 0; j < 4; j++) {
            w[0][j] = d[0][j] - d[2][j];
            w[1][j] = d[1][j] + d[2][j];
            w[2][j] = d[2][j] - d[1][j];
            w[3][j] = d[1][j] - d[3][j];
        }
#pragma unroll
        for (int i = 0; i < 4; i++) {
            float v0 = w[i][0] - w[i][2];
            float v1 = w[i][1] + w[i][2];
            float v2 = w[i][2] - w[i][1];
            float v3 = w[i][1] - w[i][3];
            g_V[((size_t)(i*4+0)*1024 + ci)*NTILE + t] = v0;
            g_V[((size_t)(i*4+1)*1024 + ci)*NTILE + t] = v1;
            g_V[((size_t)(i*4+2)*1024 + ci)*NTILE + t] = v2;
            g_V[((size_t)(i*4+3)*1024 + ci)*NTILE + t] = v3;
        }
    } else {
        const int idx = (blockIdx.x - 9216) * 256 + threadIdx.x;   // 512*1024
        const int oc = idx & 511;
        const int ci = idx >> 9;
        float g[9];
#pragma unroll
        for (int j = 0; j < 9; j++) g[j] = wsrc[((size_t)oc*1024 + ci)*9 + j];

        float T[4][3];
#pragma unroll
        for (int j = 0; j < 3; j++) {
            T[0][j] = g[j];
            T[1][j] = 0.5f*(g[j] + g[3+j] + g[6+j]);
            T[2][j] = 0.5f*(g[j] - g[3+j] + g[6+j]);
            T[3][j] = g[6+j];
        }
#pragma unroll
        for (int i = 0; i < 4; i++) {
            float u0 = T[i][0];
            float u1 = 0.5f*(T[i][0] + T[i][1] + T[i][2]);
            float u2 = 0.5f*(T[i][0] - T[i][1] + T[i][2]);
            float u3 = T[i][2];
            g_U[((size_t)(i*4+0)*1024 + ci)*512 + oc] = u0;
            g_U[((size_t)(i*4+1)*1024 + ci)*512 + oc] = u1;
            g_U[((size_t)(i*4+2)*1024 + ci)*512 + oc] = u2;
            g_U[((size_t)(i*4+3)*1024 + ci)*512 + oc] = u3;
        }
    }
}

// ---------------- winograd GEMM: warp-uniform A operand (UR candidate), per-lane B ----------------
// CTA 256 thr = 8 warps. Warp w: m-slice [m0 + w*16, +16), all 256 oc.
// Lane l: 8 oc (4 f32x2 pairs). accs = 16 m x 4 pairs = 64 f32x2.
// A (x) loads are warp-uniform shared addresses -> broadcast, no swizzle needed;
// ptxas uniformity analysis can place them in UR -> FFMA2 rt2 instead of rt3.
__global__ void __launch_bounds__(256, 1) wino_gemm_kernel() {
    __shared__ float2 xa[2][8][128];     // x pairs, duplicated {v,v}
    __shared__ float  wb[2][8][256];     // weights [k][oc]

    const int tid  = threadIdx.x;
    const int lane = tid & 31;
    const int wid  = tid >> 5;           // 0..7 -> m slice
    const int ms   = wid * 16;
    const int m0   = blockIdx.x * 128;
    const int ocb  = blockIdx.y * 256;
    const int z    = blockIdx.z;

    const float* Ag = g_V + (size_t)z * 1024 * NTILE;
    const float* Bg = g_U + (size_t)z * 1024 * 512;

    unsigned long long acc[16][4];
#pragma unroll
    for (int j = 0; j < 16; j++)
#pragma unroll
        for (int q = 0; q < 4; q++) acc[j][q] = 0ull;

    float av[4], bv[8];
    // prefetch k-block 0
#pragma unroll
    for (int i = 0; i < 4; i++) {
        int idx = i*256 + tid;
        av[i] = Ag[(size_t)(idx >> 7) * NTILE + m0 + (idx & 127)];
    }
#pragma unroll
    for (int i = 0; i < 8; i++) bv[i] = Bg[(size_t)i * 512 + ocb + tid];
#pragma unroll
    for (int i = 0; i < 4; i++) {
        int idx = i*256 + tid;
        xa[0][idx >> 7][idx & 127] = make_float2(av[i], av[i]);
    }
#pragma unroll
    for (int i = 0; i < 8; i++) wb[0][i][tid] = bv[i];

    for (int it = 0; it < 128; it++) {
        const int b = it & 1;
        if (it < 127) {
            const int k0 = (it + 1) * 8;
#pragma unroll
            for (int i = 0; i < 4; i++) {
                int idx = i*256 + tid;
                av[i] = Ag[(size_t)(k0 + (idx >> 7)) * NTILE + m0 + (idx & 127)];
            }
#pragma unroll
            for (int i = 0; i < 8; i++) bv[i] = Bg[(size_t)(k0 + i) * 512 + ocb + tid];
        }
        __syncthreads();    // buffer b staged

#pragma unroll
        for (int kk = 0; kk < 8; kk++) {
            // per-lane weights: 4 f32x2 pairs (2x LDS.128, conflict-free)
            const unsigned long long* wp =
                (const unsigned long long*)&wb[b][kk][lane * 8];
            const unsigned long long w0 = wp[0], w1 = wp[1], w2 = wp[2], w3 = wp[3];
            // warp-uniform x pairs (broadcast loads; UR candidates)
            const unsigned long long* xp =
                (const unsigned long long*)&xa[b][kk][ms];
#pragma unroll
            for (int j = 0; j < 16; j++) {
                const unsigned long long xu = xp[j];
                ffma2(acc[j][0], w0, xu);
                ffma2(acc[j][1], w1, xu);
                ffma2(acc[j][2], w2, xu);
                ffma2(acc[j][3], w3, xu);
            }
        }

        if (it < 127) {
            __syncthreads();
            const int nb = b ^ 1;
#pragma unroll
            for (int i = 0; i < 4; i++) {
                int idx = i*256 + tid;
                xa[nb][idx >> 7][idx & 127] = make_float2(av[i], av[i]);
            }
#pragma unroll
            for (int i = 0; i < 8; i++) wb[nb][i][tid] = bv[i];
        }
    }

    // write M[z][oc][m]: lane owns oc = ocb + lane*8 + {0..7}, m = m0 + ms + j
#pragma unroll
    for (int q = 0; q < 4; q++) {
        const int oc0 = ocb + lane*8 + 2*q;
        float* base0 = g_M + ((size_t)z*512 + oc0) * NTILE + m0 + ms;
        float* base1 = base0 + NTILE;
#pragma unroll
        for (int j = 0; j < 16; j++) {
            base0[j] = f2_lo(acc[j][q]);
            base1[j] = f2_hi(acc[j][q]);
        }
    }
}

// ---------------- F(2,3) output transform: Y = A^T M A, + bias, relu ----------------
__global__ void __launch_bounds__(256) wino_out_kernel(const float* __restrict__ b_rpn) {
    const int t  = blockIdx.x * 256 + threadIdx.x;     // 0..2303
    const int oc = blockIdx.y;
    float m[16];
#pragma unroll
    for (int k = 0; k < 16; k++)
        m[k] = g_M[((size_t)k*512 + oc)*NTILE + t];

    float P0[4], P1[4];
#pragma unroll
    for (int j = 0; j < 4; j++) {
        P0[j] = m[j] + m[4+j] + m[8+j];
        P1[j] = m[4+j] - m[8+j] - m[12+j];
    }
    const float bias = b_rpn[oc];
    float y00 = P0[0] + P0[1] + P0[2] + bias;
    float y01 = P0[1] - P0[2] - P0[3] + bias;
    float y10 = P1[0] + P1[1] + P1[2] + bias;
    float y11 = P1[1] - P1[2] - P1[3] + bias;

    const int ty = t / 48, tx = t % 48;
    float* hp = g_h + (size_t)oc * NPIX + (2*ty)*96 + 2*tx;
    hp[0]    = y00 > 0.f ? y00 : 0.f;
    hp[1]    = y01 > 0.f ? y01 : 0.f;
    hp[96]   = y10 > 0.f ? y10 : 0.f;
    hp[97]   = y11 > 0.f ? y11 : 0.f;
}

// ---------------- 1x1 convs + anchor decode + softmax keys (fused) ----------------
__global__ void __launch_bounds__(128) conv1x1_decode_kernel(
        const float* __restrict__ wcls, const float* __restrict__ bcls,
        const float* __restrict__ wreg, const float* __restrict__ breg,
        const float* __restrict__ anchors) {
    int p = blockIdx.x * 128 + threadIdx.x;   // 9216 pixels (72 blocks)
    float acc[54];
#pragma unroll
    for (int o = 0; o < 54; o++) acc[o] = 0.f;

    for (int c = 0; c < 512; c += 4) {
        float v0 = g_h[(c+0)*NPIX + p];
        float v1 = g_h[(c+1)*NPIX + p];
        float v2 = g_h[(c+2)*NPIX + p];
        float v3 = g_h[(c+3)*NPIX + p];
#pragma unroll
        for (int o = 0; o < 18; o++) {
            float4 w = *(const float4*)(wcls + o*512 + c);
            acc[o] += w.x*v0; acc[o] += w.y*v1; acc[o] += w.z*v2; acc[o] += w.w*v3;
        }
#pragma unroll
        for (int o = 0; o < 36; o++) {
            float4 w = *(const float4*)(wreg + o*512 + c);
            acc[18+o] += w.x*v0; acc[18+o] += w.y*v1; acc[18+o] += w.z*v2; acc[18+o] += w.w*v3;
        }
    }
#pragma unroll
    for (int o = 0; o < 18; o++) g_cls[o*NPIX + p] = acc[o] + bcls[o];

#pragma unroll
    for (int k = 0; k < 9; k++) {
        const int a = p*9 + k;
        float c0 = acc[2*k    ] + bcls[2*k    ];
        float c1 = acc[2*k + 1] + bcls[2*k + 1];
        float r0 = acc[18 + 4*k + 0] + breg[4*k + 0];
        float r1 = acc[18 + 4*k + 1] + breg[4*k + 1];
        float r2 = acc[18 + 4*k + 2] + breg[4*k + 2];
        float r3 = acc[18 + 4*k + 3] + breg[4*k + 3];

        float4 an = ((const float4*)anchors)[a];
        float aw = an.z - an.x + 1.f;
        float ah = an.w - an.y + 1.f;
        float ax = an.x + 0.5f*(aw - 1.f);
        float ay = an.y + 0.5f*(ah - 1.f);
        float px = ax + aw * r0;
        float py = ay + ah * r1;
        float pw = aw * expf(r2);
        float ph = ah * expf(r3);
        float x0 = px - 0.5f*(pw - 1.f);
        float y0 = py - 0.5f*(ph - 1.f);
        float x1 = px + 0.5f*(pw - 1.f);
        float y1 = py + 0.5f*(ph - 1.f);

        ((float4*)g_prop)[a] = make_float4(x0, y0, x1, y1);
        float4 cb;
        cb.x = fminf(fmaxf(x0, 0.f), 1535.f);
        cb.y = fminf(fmaxf(y0, 0.f), 1535.f);
        cb.z = fminf(fmaxf(x1, 0.f), 1535.f);
        cb.w = fminf(fmaxf(y1, 0.f), 1535.f);
        ((float4*)g_bbox)[a] = cb;

        float m  = fmaxf(c0, c1);
        float e0 = expf(c0 - m);
        float e1 = expf(c1 - m);
        float prob = e1 / (e0 + e1);
        g_keys32[a] = ~__float_as_uint(prob);
        g_vals32[a] = a;
    }
}

// ---------------- fused greedy NMS (reads sorted keys/vals directly) ----------------
__global__ void __launch_bounds__(256) nms_fused_kernel(float* __restrict__ outF,
                                                        float* __restrict__ outP) {
    extern __shared__ float4 sb4[];                 // boxes[PRE_N]
    float* sarea = (float*)(sb4 + PRE_N);           // areas[PRE_N]
    __shared__ int kept[POS_N];
    __shared__ unsigned long long remv;
    __shared__ unsigned long long mw[64];
    __shared__ int kc;

    const int tid = threadIdx.x;
    for (int i = tid; i < PRE_N; i += 256) {
        int a = g_vals32_s[i];
        float4 b = ((const float4*)g_bbox)[a];
        sb4[i] = b;
        sarea[i] = (b.z - b.x + 1.f) * (b.w - b.y + 1.f);
    }
    if (tid == 0) kc = 0;
    __syncthreads();

    for (int g = 0; g < NWORDS; g++) {
        const int base = g * 64;
        const int lim  = min(64, PRE_N - base);
        if (tid == 0) remv = 0ull;
        if (tid < 64) mw[tid] = 0ull;
        __syncthreads();

        {
            const int c  = tid & 63;
            const int ks = tid >> 6;
            if (c < lim) {
                float4 bc = sb4[base + c];
                float  ac = sarea[base + c];
                bool sup = false;
                for (int t = ks; t < kc; t += 4) {
                    int i = kept[t];
                    float4 bi = sb4[i];
                    float iw = fminf(bi.z, bc.z) - fmaxf(bi.x, bc.x) + 1.f;
                    float ih = fminf(bi.w, bc.w) - fmaxf(bi.y, bc.y) + 1.f;
                    iw = fmaxf(iw, 0.f);
                    ih = fmaxf(ih, 0.f);
                    float inter = iw * ih;
                    float iou = inter / (sarea[i] + ac - inter);
                    if (iou > 0.7f) { sup = true; break; }
                }
                if (sup) atomicOr(&remv, 1ull << c);
            }
        }
        for (int e = tid; e < 64*64; e += 256) {
            const int r = e >> 6, c = e & 63;
            if (c > r && c < lim && r < lim) {
                float4 br = sb4[base + r];
                float4 bc = sb4[base + c];
                float iw = fminf(br.z, bc.z) - fmaxf(br.x, bc.x) + 1.f;
                float ih = fminf(br.w, bc.w) - fmaxf(br.y, bc.y) + 1.f;
                iw = fmaxf(iw, 0.f);
                ih = fmaxf(ih, 0.f);
                float inter = iw * ih;
                float iou = inter / (sarea[base + r] + sarea[base + c] - inter);
                if (iou > 0.7f) atomicOr(&mw[r], 1ull << c);
            }
        }
        __syncthreads();

        if (tid == 0) {
            unsigned long long limmask = (lim == 64) ? ~0ull : ((1ull << lim) - 1ull);
            unsigned long long avail = ~remv & limmask;
            int k = kc;
            while (avail && k < POS_N) {
                int b = __ffsll((long long)avail) - 1;
                kept[k++] = base + b;
                avail &= ~(mw[b] | (1ull << b));
            }
            kc = k;
        }
        __syncthreads();
        if (kc >= POS_N) break;
    }

    for (int rI = tid; rI < POS_N; rI += 256) {
        if (rI < kc) {
            int a = kept[rI];
            float4 b = sb4[a];
            outF[rI*4 + 0] = b.x;
            outF[rI*4 + 1] = b.y;
            outF[rI*4 + 2] = b.z;
            outF[rI*4 + 3] = b.w;
            outP[rI] = __uint_as_float(~g_keys32_s[a]);
        } else {
            outF[rI*4 + 0] = 0.f; outF[rI*4 + 1] = 0.f;
            outF[rI*4 + 2] = 0.f; outF[rI*4 + 3] = 0.f;
            outP[rI] = 0.f;
        }
    }
}

// ---------------- gather proposals[valid_idx], cls[valid_idx] ----------------
__global__ void gather_valid_kernel(const int* __restrict__ vidx, int nv,
                                    float* __restrict__ out) {
    int i = blockIdx.x * 256 + threadIdx.x;
    if (i >= nv) return;
    int a = vidx[i];
    out[i*4 + 0] = g_prop[a*4 + 0];
    out[i*4 + 1] = g_prop[a*4 + 1];
    out[i*4 + 2] = g_prop[a*4 + 2];
    out[i*4 + 3] = g_prop[a*4 + 3];
    int pix = a / 9, k = a % 9;
    out[(long long)nv*4 + i*2 + 0] = g_cls[(k*2 + 0)*NPIX + pix];
    out[(long long)nv*4 + i*2 + 1] = g_cls[(k*2 + 1)*NPIX + pix];
}

// ---------------- host ----------------
extern "C" void kernel_launch(void* const* d_in, const int* in_sizes, int n_in,
                              void* d_out, int out_size) {
    int ix=-1, iwr=-1, ibr=-1, iwc=-1, ibc=-1, iwg=-1, ibg=-1, ian=-1, ivi=-1;
    int nv = (out_size - (POS_N*4 + POS_N)) / 6;
    for (int i = 0; i < n_in; i++) {
        int s = in_sizes[i];
        if      (s == 1024*NPIX)     ix  = i;
        else if (s == 512*1024*9)    iwr = i;
        else if (s == 512)           ibr = i;
        else if (s == 18*512)        iwc = i;
        else if (s == 18)            ibc = i;
        else if (s == 36*512)        iwg = i;
        else if (s == 36)            ibg = i;
        else if (s == NANCH*4)       ian = i;
        else if (s == nv)            ivi = i;
    }
    if (ivi < 0) ivi = 8;

    const float* x      = (const float*)d_in[ix];
    const float* w_rpn  = (const float*)d_in[iwr];
    const float* b_rpn  = (const float*)d_in[ibr];
    const float* w_cls  = (const float*)d_in[iwc];
    const float* b_cls  = (const float*)d_in[ibc];
    const float* w_reg  = (const float*)d_in[iwg];
    const float* b_reg  = (const float*)d_in[ibg];
    const float* anch   = (const float*)d_in[ian];
    const int*   vidx   = (const int*)d_in[ivi];
    float* out = (float*)d_out;

    const int NMS_SMEM = PRE_N * (int)sizeof(float4) + PRE_N * (int)sizeof(float); // 120000
    cudaFuncSetAttribute(nms_fused_kernel,
                         cudaFuncAttributeMaxDynamicSharedMemorySize, NMS_SMEM);

    // capture slot is launch #4 -> wino_gemm profiles there (direct measurement)
    prep_kernel<<<9216 + 2048, 256>>>(x, w_rpn);
    noop_kernel<<<1, 32>>>();
    noop_kernel<<<1, 32>>>();
    wino_gemm_kernel<<<dim3(18, 2, 16), 256>>>();
    wino_out_kernel<<<dim3(9, 512), 256>>>(b_rpn);
    conv1x1_decode_kernel<<<NPIX/128, 128>>>(w_cls, b_cls, w_reg, b_reg, anch);

    void *d_temp, *d_kin, *d_kout, *d_vin, *d_vout;
    cudaGetSymbolAddress(&d_temp, g_cub_temp);
    cudaGetSymbolAddress(&d_kin,  g_keys32);
    cudaGetSymbolAddress(&d_kout, g_keys32_s);
    cudaGetSymbolAddress(&d_vin,  g_vals32);
    cudaGetSymbolAddress(&d_vout, g_vals32_s);
    size_t temp_bytes = sizeof(g_cub_temp);
    cub::DeviceRadixSort::SortPairs(d_temp, temp_bytes,
                                    (const unsigned*)d_kin, (unsigned*)d_kout,
                                    (const int*)d_vin, (int*)d_vout,
                                    NANCH, 0, 32, (cudaStream_t)0);

    nms_fused_kernel<<<1, 256, NMS_SMEM>>>(out + (long long)nv*6,
                                           out + (long long)nv*6 + POS_N*4);
    gather_valid_kernel<<<(nv + 255)/256, 256>>>(vidx, nv, out);
}

// round 14
// speedup vs baseline: 1.0127x; 1.0127x over previous
#include <cuda_runtime.h>
#include <cub/cub.cuh>

#define NPIX   9216     // 96*96
#define NANCH  82944    // NPIX*9
#define PRE_N  6000
#define POS_N  300
#define NWORDS 94       // ceil(6000/64)
#define NTILE  2304     // 48*48 winograd 2x2 tiles

// ---------------- scratch (static device memory; no allocation) ----------------
__device__ float g_V[16*1024*NTILE];        // winograd input  [k16][ci][tile]
__device__ float g_U[16*1024*512];          // winograd weight [k16][ci][oc]
__device__ float g_M[16*512*NTILE];         // winograd product [k16][oc][tile]
__device__ float g_h[512*NPIX];             // relu(conv3x3) output [oc][pix]
__device__ float g_cls[18*NPIX];            // cls logits [ch][pix] (for gather_valid)
__device__ float g_prop[NANCH*4];           // unclipped proposals
__device__ float g_bbox[NANCH*4];           // clipped boxes
__device__ unsigned g_keys32[NANCH];
__device__ int      g_vals32[NANCH];
__device__ unsigned g_keys32_s[NANCH];
__device__ int      g_vals32_s[NANCH];
__device__ unsigned char g_cub_temp[8<<20];

// ---------------- packed f32x2 helpers ----------------
__device__ __forceinline__ void ffma2(unsigned long long &d,
                                      unsigned long long a,
                                      unsigned long long b) {
    asm("fma.rn.f32x2 %0, %1, %2, %0;" : "+l"(d) : "l"(a), "l"(b));
}
__device__ __forceinline__ float f2_lo(unsigned long long v) {
    return __uint_as_float((unsigned)(v & 0xffffffffull));
}
__device__ __forceinline__ float f2_hi(unsigned long long v) {
    return __uint_as_float((unsigned)(v >> 32));
}

// ---------------- merged prep: input transform (blocks 0..9215) + weight transform ----------------
__global__ void __launch_bounds__(256) prep_kernel(const float* __restrict__ x,
                                                   const float* __restrict__ wsrc) {
    if (blockIdx.x < 9216) {
        // -------- F(2,3) input transform: V = B^T d B --------
        const int ci = blockIdx.x / 9;
        const int t  = (blockIdx.x % 9) * 256 + threadIdx.x;   // 0..2303
        const int ty = t / 48, tx = t % 48;
        const int r0 = 2*ty - 1, c0 = 2*tx - 1;
        const float* xp = x + (size_t)ci * NPIX;

        float d[4][4];
#pragma unroll
        for (int a = 0; a < 4; a++) {
            const int rr = r0 + a;
            const bool rok = (unsigned)rr < 96u;
#pragma unroll
            for (int b = 0; b < 4; b++) {
                const int cc = c0 + b;
                d[a][b] = (rok && (unsigned)cc < 96u) ? xp[rr*96 + cc] : 0.f;
            }
        }
        float w[4][4];
#pragma unroll
        for (int j = 0; j < 4; j++) {
            w[0][j] = d[0][j] - d[2][j];
            w[1][j] = d[1][j] + d[2][j];
            w[2][j] = d[2][j] - d[1][j];
            w[3][j] = d[1][j] - d[3][j];
        }
#pragma unroll
        for (int i = 0; i < 4; i++) {
            float v0 = w[i][0] - w[i][2];
            float v1 = w[i][1] + w[i][2];
            float v2 = w[i][2] - w[i][1];
            float v3 = w[i][1] - w[i][3];
            g_V[((size_t)(i*4+0)*1024 + ci)*NTILE + t] = v0;
            g_V[((size_t)(i*4+1)*1024 + ci)*NTILE + t] = v1;
            g_V[((size_t)(i*4+2)*1024 + ci)*NTILE + t] = v2;
            g_V[((size_t)(i*4+3)*1024 + ci)*NTILE + t] = v3;
        }
    } else {
        // -------- F(2,3) weight transform: U = G g G^T --------
        const int idx = (blockIdx.x - 9216) * 256 + threadIdx.x;   // 512*1024
        const int oc = idx & 511;
        const int ci = idx >> 9;
        float g[9];
#pragma unroll
        for (int j = 0; j < 9; j++) g[j] = wsrc[((size_t)oc*1024 + ci)*9 + j];

        float T[4][3];
#pragma unroll
        for (int j = 0; j < 3; j++) {
            T[0][j] = g[j];
            T[1][j] = 0.5f*(g[j] + g[3+j] + g[6+j]);
            T[2][j] = 0.5f*(g[j] - g[3+j] + g[6+j]);
            T[3][j] = g[6+j];
        }
#pragma unroll
        for (int i = 0; i < 4; i++) {
            float u0 = T[i][0];
            float u1 = 0.5f*(T[i][0] + T[i][1] + T[i][2]);
            float u2 = 0.5f*(T[i][0] - T[i][1] + T[i][2]);
            float u3 = T[i][2];
            g_U[((size_t)(i*4+0)*1024 + ci)*512 + oc] = u0;
            g_U[((size_t)(i*4+1)*1024 + ci)*512 + oc] = u1;
            g_U[((size_t)(i*4+2)*1024 + ci)*512 + oc] = u2;
            g_U[((size_t)(i*4+3)*1024 + ci)*512 + oc] = u3;
        }
    }
}

// ---------------- winograd GEMM, k8 blocks, XOR-swizzled A, LDS.128 reads ----------------
// (round-8/9 variant: measured 862 us, ~98% of FFMA2 rt3 issue floor)
__global__ void __launch_bounds__(256, 1) wino_gemm_kernel() {
    __shared__ float2 xa[2][8][128];
    __shared__ float  wb[2][8][256];

    const int tid = threadIdx.x;
    const int og  = tid >> 3;        // 0..31
    const int pg  = tid & 7;         // 0..7 -> 16 m each
    const int m0  = blockIdx.x * 128;
    const int ocb = blockIdx.y * 256;
    const int z   = blockIdx.z;

    const float* Ag = g_V + (size_t)z * 1024 * NTILE;
    const float* Bg = g_U + (size_t)z * 1024 * 512;

    unsigned long long acc[16][4];
#pragma unroll
    for (int p = 0; p < 16; p++)
#pragma unroll
        for (int q = 0; q < 4; q++) acc[p][q] = 0ull;

    float av[4], bv[8];
    int aphys[4];
#pragma unroll
    for (int i = 0; i < 4; i++) {
        const int idx = i*256 + tid;
        const int mel = idx & 127;
        aphys[i] = (idx >> 7) * 128 + (mel & 0x70) + ((mel & 15) ^ ((mel >> 3) & 14));
    }

#pragma unroll
    for (int i = 0; i < 4; i++) {
        int idx = i*256 + tid;
        av[i] = Ag[(size_t)(idx >> 7) * NTILE + m0 + (idx & 127)];
    }
#pragma unroll
    for (int i = 0; i < 8; i++) bv[i] = Bg[(size_t)i * 512 + ocb + tid];
#pragma unroll
    for (int i = 0; i < 4; i++)
        (&xa[0][0][0])[aphys[i]] = make_float2(av[i], av[i]);
#pragma unroll
    for (int i = 0; i < 8; i++) wb[0][i][tid] = bv[i];

    const int sw = pg * 2;   // reader XOR swizzle (even)

    for (int it = 0; it < 128; it++) {
        const int b = it & 1;
        if (it < 127) {
            const int k0 = (it + 1) * 8;
#pragma unroll
            for (int i = 0; i < 4; i++) {
                int idx = i*256 + tid;
                av[i] = Ag[(size_t)(k0 + (idx >> 7)) * NTILE + m0 + (idx & 127)];
            }
#pragma unroll
            for (int i = 0; i < 8; i++) bv[i] = Bg[(size_t)(k0 + i) * 512 + ocb + tid];
        }
        __syncthreads();    // buffer b staged

#pragma unroll
        for (int kk = 0; kk < 8; kk++) {
            unsigned long long xr[16];
#pragma unroll
            for (int j = 0; j < 8; j++) {
                const float2* src = &xa[b][kk][pg*16 + ((2*j) ^ sw)];
                float4 v = *(const float4*)src;
                xr[2*j]   = *(unsigned long long*)&v.x;
                xr[2*j+1] = *(unsigned long long*)&v.z;
            }
            const unsigned long long* wp =
                (const unsigned long long*)&wb[b][kk][og*8];
            const unsigned long long w0 = wp[0], w1 = wp[1], w2 = wp[2], w3 = wp[3];
#pragma unroll
            for (int p = 0; p < 16; p++) {
                ffma2(acc[p][0], w0, xr[p]);
                ffma2(acc[p][1], w1, xr[p]);
                ffma2(acc[p][2], w2, xr[p]);
                ffma2(acc[p][3], w3, xr[p]);
            }
        }

        if (it < 127) {
            __syncthreads();
            const int nb = b ^ 1;
#pragma unroll
            for (int i = 0; i < 4; i++)
                (&xa[nb][0][0])[aphys[i]] = make_float2(av[i], av[i]);
#pragma unroll
            for (int i = 0; i < 8; i++) wb[nb][i][tid] = bv[i];
        }
    }

#pragma unroll
    for (int q = 0; q < 4; q++) {
        const int oc0 = ocb + og*8 + 2*q;
        float* base0 = g_M + ((size_t)z*512 + oc0) * NTILE + m0 + pg*16;
        float* base1 = base0 + NTILE;
#pragma unroll
        for (int p = 0; p < 16; p++) {
            base0[p] = f2_lo(acc[p][q]);
            base1[p] = f2_hi(acc[p][q]);
        }
    }
}

// ---------------- F(2,3) output transform: Y = A^T M A, + bias, relu ----------------
__global__ void __launch_bounds__(256) wino_out_kernel(const float* __restrict__ b_rpn) {
    const int t  = blockIdx.x * 256 + threadIdx.x;     // 0..2303
    const int oc = blockIdx.y;
    float m[16];
#pragma unroll
    for (int k = 0; k < 16; k++)
        m[k] = g_M[((size_t)k*512 + oc)*NTILE + t];

    float P0[4], P1[4];
#pragma unroll
    for (int j = 0; j < 4; j++) {
        P0[j] = m[j] + m[4+j] + m[8+j];
        P1[j] = m[4+j] - m[8+j] - m[12+j];
    }
    const float bias = b_rpn[oc];
    float y00 = P0[0] + P0[1] + P0[2] + bias;
    float y01 = P0[1] - P0[2] - P0[3] + bias;
    float y10 = P1[0] + P1[1] + P1[2] + bias;
    float y11 = P1[1] - P1[2] - P1[3] + bias;

    const int ty = t / 48, tx = t % 48;
    float* hp = g_h + (size_t)oc * NPIX + (2*ty)*96 + 2*tx;
    hp[0]    = y00 > 0.f ? y00 : 0.f;
    hp[1]    = y01 > 0.f ? y01 : 0.f;
    hp[96]   = y10 > 0.f ? y10 : 0.f;
    hp[97]   = y11 > 0.f ? y11 : 0.f;
}

// ---------------- 1x1 convs + anchor decode + softmax keys (fused) ----------------
__global__ void __launch_bounds__(128) conv1x1_decode_kernel(
        const float* __restrict__ wcls, const float* __restrict__ bcls,
        const float* __restrict__ wreg, const float* __restrict__ breg,
        const float* __restrict__ anchors) {
    int p = blockIdx.x * 128 + threadIdx.x;   // 9216 pixels (72 blocks)
    float acc[54];
#pragma unroll
    for (int o = 0; o < 54; o++) acc[o] = 0.f;

    for (int c = 0; c < 512; c += 4) {
        float v0 = g_h[(c+0)*NPIX + p];
        float v1 = g_h[(c+1)*NPIX + p];
        float v2 = g_h[(c+2)*NPIX + p];
        float v3 = g_h[(c+3)*NPIX + p];
#pragma unroll
        for (int o = 0; o < 18; o++) {
            float4 w = *(const float4*)(wcls + o*512 + c);
            acc[o] += w.x*v0; acc[o] += w.y*v1; acc[o] += w.z*v2; acc[o] += w.w*v3;
        }
#pragma unroll
        for (int o = 0; o < 36; o++) {
            float4 w = *(const float4*)(wreg + o*512 + c);
            acc[18+o] += w.x*v0; acc[18+o] += w.y*v1; acc[18+o] += w.z*v2; acc[18+o] += w.w*v3;
        }
    }
#pragma unroll
    for (int o = 0; o < 18; o++) g_cls[o*NPIX + p] = acc[o] + bcls[o];

#pragma unroll
    for (int k = 0; k < 9; k++) {
        const int a = p*9 + k;
        float c0 = acc[2*k    ] + bcls[2*k    ];
        float c1 = acc[2*k + 1] + bcls[2*k + 1];
        float r0 = acc[18 + 4*k + 0] + breg[4*k + 0];
        float r1 = acc[18 + 4*k + 1] + breg[4*k + 1];
        float r2 = acc[18 + 4*k + 2] + breg[4*k + 2];
        float r3 = acc[18 + 4*k + 3] + breg[4*k + 3];

        float4 an = ((const float4*)anchors)[a];
        float aw = an.z - an.x + 1.f;
        float ah = an.w - an.y + 1.f;
        float ax = an.x + 0.5f*(aw - 1.f);
        float ay = an.y + 0.5f*(ah - 1.f);
        float px = ax + aw * r0;
        float py = ay + ah * r1;
        float pw = aw * expf(r2);
        float ph = ah * expf(r3);
        float x0 = px - 0.5f*(pw - 1.f);
        float y0 = py - 0.5f*(ph - 1.f);
        float x1 = px + 0.5f*(pw - 1.f);
        float y1 = py + 0.5f*(ph - 1.f);

        ((float4*)g_prop)[a] = make_float4(x0, y0, x1, y1);
        float4 cb;
        cb.x = fminf(fmaxf(x0, 0.f), 1535.f);
        cb.y = fminf(fmaxf(y0, 0.f), 1535.f);
        cb.z = fminf(fmaxf(x1, 0.f), 1535.f);
        cb.w = fminf(fmaxf(y1, 0.f), 1535.f);
        ((float4*)g_bbox)[a] = cb;

        float m  = fmaxf(c0, c1);
        float e0 = expf(c0 - m);
        float e1 = expf(c1 - m);
        float prob = e1 / (e0 + e1);
        g_keys32[a] = ~__float_as_uint(prob);
        g_vals32[a] = a;
    }
}

// ---------------- fused greedy NMS (reads sorted keys/vals directly) ----------------
__global__ void __launch_bounds__(256) nms_fused_kernel(float* __restrict__ outF,
                                                        float* __restrict__ outP) {
    extern __shared__ float4 sb4[];                 // boxes[PRE_N]
    float* sarea = (float*)(sb4 + PRE_N);           // areas[PRE_N]
    __shared__ int kept[POS_N];
    __shared__ unsigned long long remv;
    __shared__ unsigned long long mw[64];
    __shared__ int kc;

    const int tid = threadIdx.x;
    for (int i = tid; i < PRE_N; i += 256) {
        int a = g_vals32_s[i];
        float4 b = ((const float4*)g_bbox)[a];
        sb4[i] = b;
        sarea[i] = (b.z - b.x + 1.f) * (b.w - b.y + 1.f);
    }
    if (tid == 0) kc = 0;
    __syncthreads();

    for (int g = 0; g < NWORDS; g++) {
        const int base = g * 64;
        const int lim  = min(64, PRE_N - base);
        if (tid == 0) remv = 0ull;
        if (tid < 64) mw[tid] = 0ull;
        __syncthreads();

        {
            const int c  = tid & 63;
            const int ks = tid >> 6;
            if (c < lim) {
                float4 bc = sb4[base + c];
                float  ac = sarea[base + c];
                bool sup = false;
                for (int t = ks; t < kc; t += 4) {
                    int i = kept[t];
                    float4 bi = sb4[i];
                    float iw = fminf(bi.z, bc.z) - fmaxf(bi.x, bc.x) + 1.f;
                    float ih = fminf(bi.w, bc.w) - fmaxf(bi.y, bc.y) + 1.f;
                    iw = fmaxf(iw, 0.f);
                    ih = fmaxf(ih, 0.f);
                    float inter = iw * ih;
                    float iou = inter / (sarea[i] + ac - inter);
                    if (iou > 0.7f) { sup = true; break; }
                }
                if (sup) atomicOr(&remv, 1ull << c);
            }
        }
        for (int e = tid; e < 64*64; e += 256) {
            const int r = e >> 6, c = e & 63;
            if (c > r && c < lim && r < lim) {
                float4 br = sb4[base + r];
                float4 bc = sb4[base + c];
                float iw = fminf(br.z, bc.z) - fmaxf(br.x, bc.x) + 1.f;
                float ih = fminf(br.w, bc.w) - fmaxf(br.y, bc.y) + 1.f;
                iw = fmaxf(iw, 0.f);
                ih = fmaxf(ih, 0.f);
                float inter = iw * ih;
                float iou = inter / (sarea[base + r] + sarea[base + c] - inter);
                if (iou > 0.7f) atomicOr(&mw[r], 1ull << c);
            }
        }
        __syncthreads();

        if (tid == 0) {
            unsigned long long limmask = (lim == 64) ? ~0ull : ((1ull << lim) - 1ull);
            unsigned long long avail = ~remv & limmask;
            int k = kc;
            while (avail && k < POS_N) {
                int b = __ffsll((long long)avail) - 1;
                kept[k++] = base + b;
                avail &= ~(mw[b] | (1ull << b));
            }
            kc = k;
        }
        __syncthreads();
        if (kc >= POS_N) break;
    }

    for (int rI = tid; rI < POS_N; rI += 256) {
        if (rI < kc) {
            int a = kept[rI];
            float4 b = sb4[a];
            outF[rI*4 + 0] = b.x;
            outF[rI*4 + 1] = b.y;
            outF[rI*4 + 2] = b.z;
            outF[rI*4 + 3] = b.w;
            outP[rI] = __uint_as_float(~g_keys32_s[a]);
        } else {
            outF[rI*4 + 0] = 0.f; outF[rI*4 + 1] = 0.f;
            outF[rI*4 + 2] = 0.f; outF[rI*4 + 3] = 0.f;
            outP[rI] = 0.f;
        }
    }
}

// ---------------- gather proposals[valid_idx], cls[valid_idx] ----------------
__global__ void gather_valid_kernel(const int* __restrict__ vidx, int nv,
                                    float* __restrict__ out) {
    int i = blockIdx.x * 256 + threadIdx.x;
    if (i >= nv) return;
    int a = vidx[i];
    out[i*4 + 0] = g_prop[a*4 + 0];
    out[i*4 + 1] = g_prop[a*4 + 1];
    out[i*4 + 2] = g_prop[a*4 + 2];
    out[i*4 + 3] = g_prop[a*4 + 3];
    int pix = a / 9, k = a % 9;
    out[(long long)nv*4 + i*2 + 0] = g_cls[(k*2 + 0)*NPIX + pix];
    out[(long long)nv*4 + i*2 + 1] = g_cls[(k*2 + 1)*NPIX + pix];
}

// ---------------- host ----------------
extern "C" void kernel_launch(void* const* d_in, const int* in_sizes, int n_in,
                              void* d_out, int out_size) {
    int ix=-1, iwr=-1, ibr=-1, iwc=-1, ibc=-1, iwg=-1, ibg=-1, ian=-1, ivi=-1;
    int nv = (out_size - (POS_N*4 + POS_N)) / 6;
    for (int i = 0; i < n_in; i++) {
        int s = in_sizes[i];
        if      (s == 1024*NPIX)     ix  = i;
        else if (s == 512*1024*9)    iwr = i;
        else if (s == 512)           ibr = i;
        else if (s == 18*512)        iwc = i;
        else if (s == 18)            ibc = i;
        else if (s == 36*512)        iwg = i;
        else if (s == 36)            ibg = i;
        else if (s == NANCH*4)       ian = i;
        else if (s == nv)            ivi = i;
    }
    if (ivi < 0) ivi = 8;

    const float* x      = (const float*)d_in[ix];
    const float* w_rpn  = (const float*)d_in[iwr];
    const float* b_rpn  = (const float*)d_in[ibr];
    const float* w_cls  = (const float*)d_in[iwc];
    const float* b_cls  = (const float*)d_in[ibc];
    const float* w_reg  = (const float*)d_in[iwg];
    const float* b_reg  = (const float*)d_in[ibg];
    const float* anch   = (const float*)d_in[ian];
    const int*   vidx   = (const int*)d_in[ivi];
    float* out = (float*)d_out;

    const int NMS_SMEM = PRE_N * (int)sizeof(float4) + PRE_N * (int)sizeof(float); // 120000
    cudaFuncSetAttribute(nms_fused_kernel,
                         cudaFuncAttributeMaxDynamicSharedMemorySize, NMS_SMEM);

    prep_kernel<<<9216 + 2048, 256>>>(x, w_rpn);
    wino_gemm_kernel<<<dim3(18, 2, 16), 256>>>();
    wino_out_kernel<<<dim3(9, 512), 256>>>(b_rpn);
    conv1x1_decode_kernel<<<NPIX/128, 128>>>(w_cls, b_cls, w_reg, b_reg, anch);

    void *d_temp, *d_kin, *d_kout, *d_vin, *d_vout;
    cudaGetSymbolAddress(&d_temp, g_cub_temp);
    cudaGetSymbolAddress(&d_kin,  g_keys32);
    cudaGetSymbolAddress(&d_kout, g_keys32_s);
    cudaGetSymbolAddress(&d_vin,  g_vals32);
    cudaGetSymbolAddress(&d_vout, g_vals32_s);
    size_t temp_bytes = sizeof(g_cub_temp);
    cub::DeviceRadixSort::SortPairs(d_temp, temp_bytes,
                                    (const unsigned*)d_kin, (unsigned*)d_kout,
                                    (const int*)d_vin, (int*)d_vout,
                                    NANCH, 0, 32, (cudaStream_t)0);

    nms_fused_kernel<<<1, 256, NMS_SMEM>>>(out + (long long)nv*6,
                                           out + (long long)nv*6 + POS_N*4);
    gather_valid_kernel<<<(nv + 255)/256, 256>>>(vidx, nv, out);
}

// round 15
// speedup vs baseline: 1.1375x; 1.1232x over previous
#include <cuda_runtime.h>
#include <cub/cub.cuh>

#define NPIX   9216     // 96*96
#define NANCH  82944    // NPIX*9
#define PRE_N  6000
#define POS_N  300
#define NWORDS 94       // ceil(6000/64)
#define NTILE  2304     // 48*48 winograd 2x2 tiles

// ---------------- scratch (static device memory; no allocation) ----------------
__device__ float g_V[16*1024*NTILE];        // winograd input  [k16][ci][tile]
__device__ float g_U[16*1024*512];          // winograd weight [k16][ci][oc]
__device__ float g_M[16*512*NTILE];         // winograd product [k16][oc][tile]
__device__ float g_h[512*NPIX];             // relu(conv3x3) output [oc][pix]
__device__ float g_cls[18*NPIX];            // cls logits [ch][pix] (for gather_valid)
__device__ float g_prop[NANCH*4];           // unclipped proposals
__device__ float g_bbox[NANCH*4];           // clipped boxes
__device__ unsigned g_keys32[NANCH];
__device__ int      g_vals32[NANCH];
__device__ unsigned g_keys32_s[NANCH];
__device__ int      g_vals32_s[NANCH];
__device__ unsigned char g_cub_temp[8<<20];

// ---------------- packed f32x2 helpers ----------------
__device__ __forceinline__ void ffma2(unsigned long long &d,
                                      unsigned long long a,
                                      unsigned long long b) {
    asm("fma.rn.f32x2 %0, %1, %2, %0;" : "+l"(d) : "l"(a), "l"(b));
}
__device__ __forceinline__ float f2_lo(unsigned long long v) {
    return __uint_as_float((unsigned)(v & 0xffffffffull));
}
__device__ __forceinline__ float f2_hi(unsigned long long v) {
    return __uint_as_float((unsigned)(v >> 32));
}

// ---------------- merged prep: input transform (blocks 0..9215) + weight transform ----------------
__global__ void __launch_bounds__(256) prep_kernel(const float* __restrict__ x,
                                                   const float* __restrict__ wsrc) {
    if (blockIdx.x < 9216) {
        const int ci = blockIdx.x / 9;
        const int t  = (blockIdx.x % 9) * 256 + threadIdx.x;   // 0..2303
        const int ty = t / 48, tx = t % 48;
        const int r0 = 2*ty - 1, c0 = 2*tx - 1;
        const float* xp = x + (size_t)ci * NPIX;

        float d[4][4];
#pragma unroll
        for (int a = 0; a < 4; a++) {
            const int rr = r0 + a;
            const bool rok = (unsigned)rr < 96u;
#pragma unroll
            for (int b = 0; b < 4; b++) {
                const int cc = c0 + b;
                d[a][b] = (rok && (unsigned)cc < 96u) ? xp[rr*96 + cc] : 0.f;
            }
        }
        float w[4][4];
#pragma unroll
        for (int j = 0; j < 4; j++) {
            w[0][j] = d[0][j] - d[2][j];
            w[1][j] = d[1][j] + d[2][j];
            w[2][j] = d[2][j] - d[1][j];
            w[3][j] = d[1][j] - d[3][j];
        }
#pragma unroll
        for (int i = 0; i < 4; i++) {
            float v0 = w[i][0] - w[i][2];
            float v1 = w[i][1] + w[i][2];
            float v2 = w[i][2] - w[i][1];
            float v3 = w[i][1] - w[i][3];
            g_V[((size_t)(i*4+0)*1024 + ci)*NTILE + t] = v0;
            g_V[((size_t)(i*4+1)*1024 + ci)*NTILE + t] = v1;
            g_V[((size_t)(i*4+2)*1024 + ci)*NTILE + t] = v2;
            g_V[((size_t)(i*4+3)*1024 + ci)*NTILE + t] = v3;
        }
    } else {
        const int idx = (blockIdx.x - 9216) * 256 + threadIdx.x;   // 512*1024
        const int oc = idx & 511;
        const int ci = idx >> 9;
        float g[9];
#pragma unroll
        for (int j = 0; j < 9; j++) g[j] = wsrc[((size_t)oc*1024 + ci)*9 + j];

        float T[4][3];
#pragma unroll
        for (int j = 0; j < 3; j++) {
            T[0][j] = g[j];
            T[1][j] = 0.5f*(g[j] + g[3+j] + g[6+j]);
            T[2][j] = 0.5f*(g[j] - g[3+j] + g[6+j]);
            T[3][j] = g[6+j];
        }
#pragma unroll
        for (int i = 0; i < 4; i++) {
            float u0 = T[i][0];
            float u1 = 0.5f*(T[i][0] + T[i][1] + T[i][2]);
            float u2 = 0.5f*(T[i][0] - T[i][1] + T[i][2]);
            float u3 = T[i][2];
            g_U[((size_t)(i*4+0)*1024 + ci)*512 + oc] = u0;
            g_U[((size_t)(i*4+1)*1024 + ci)*512 + oc] = u1;
            g_U[((size_t)(i*4+2)*1024 + ci)*512 + oc] = u2;
            g_U[((size_t)(i*4+3)*1024 + ci)*512 + oc] = u3;
        }
    }
}

// ---------------- winograd GEMM, k8 blocks, XOR-swizzled A, LDS.128 reads ----------------
__global__ void __launch_bounds__(256, 1) wino_gemm_kernel() {
    __shared__ float2 xa[2][8][128];
    __shared__ float  wb[2][8][256];

    const int tid = threadIdx.x;
    const int og  = tid >> 3;        // 0..31
    const int pg  = tid & 7;         // 0..7 -> 16 m each
    const int m0  = blockIdx.x * 128;
    const int ocb = blockIdx.y * 256;
    const int z   = blockIdx.z;

    const float* Ag = g_V + (size_t)z * 1024 * NTILE;
    const float* Bg = g_U + (size_t)z * 1024 * 512;

    unsigned long long acc[16][4];
#pragma unroll
    for (int p = 0; p < 16; p++)
#pragma unroll
        for (int q = 0; q < 4; q++) acc[p][q] = 0ull;

    float av[4], bv[8];
    int aphys[4];
#pragma unroll
    for (int i = 0; i < 4; i++) {
        const int idx = i*256 + tid;
        const int mel = idx & 127;
        aphys[i] = (idx >> 7) * 128 + (mel & 0x70) + ((mel & 15) ^ ((mel >> 3) & 14));
    }

#pragma unroll
    for (int i = 0; i < 4; i++) {
        int idx = i*256 + tid;
        av[i] = Ag[(size_t)(idx >> 7) * NTILE + m0 + (idx & 127)];
    }
#pragma unroll
    for (int i = 0; i < 8; i++) bv[i] = Bg[(size_t)i * 512 + ocb + tid];
#pragma unroll
    for (int i = 0; i < 4; i++)
        (&xa[0][0][0])[aphys[i]] = make_float2(av[i], av[i]);
#pragma unroll
    for (int i = 0; i < 8; i++) wb[0][i][tid] = bv[i];

    const int sw = pg * 2;   // reader XOR swizzle (even)

    for (int it = 0; it < 128; it++) {
        const int b = it & 1;
        if (it < 127) {
            const int k0 = (it + 1) * 8;
#pragma unroll
            for (int i = 0; i < 4; i++) {
                int idx = i*256 + tid;
                av[i] = Ag[(size_t)(k0 + (idx >> 7)) * NTILE + m0 + (idx & 127)];
            }
#pragma unroll
            for (int i = 0; i < 8; i++) bv[i] = Bg[(size_t)(k0 + i) * 512 + ocb + tid];
        }
        __syncthreads();    // buffer b staged

#pragma unroll
        for (int kk = 0; kk < 8; kk++) {
            unsigned long long xr[16];
#pragma unroll
            for (int j = 0; j < 8; j++) {
                const float2* src = &xa[b][kk][pg*16 + ((2*j) ^ sw)];
                float4 v = *(const float4*)src;
                xr[2*j]   = *(unsigned long long*)&v.x;
                xr[2*j+1] = *(unsigned long long*)&v.z;
            }
            const unsigned long long* wp =
                (const unsigned long long*)&wb[b][kk][og*8];
            const unsigned long long w0 = wp[0], w1 = wp[1], w2 = wp[2], w3 = wp[3];
#pragma unroll
            for (int p = 0; p < 16; p++) {
                ffma2(acc[p][0], w0, xr[p]);
                ffma2(acc[p][1], w1, xr[p]);
                ffma2(acc[p][2], w2, xr[p]);
                ffma2(acc[p][3], w3, xr[p]);
            }
        }

        if (it < 127) {
            __syncthreads();
            const int nb = b ^ 1;
#pragma unroll
            for (int i = 0; i < 4; i++)
                (&xa[nb][0][0])[aphys[i]] = make_float2(av[i], av[i]);
#pragma unroll
            for (int i = 0; i < 8; i++) wb[nb][i][tid] = bv[i];
        }
    }

#pragma unroll
    for (int q = 0; q < 4; q++) {
        const int oc0 = ocb + og*8 + 2*q;
        float* base0 = g_M + ((size_t)z*512 + oc0) * NTILE + m0 + pg*16;
        float* base1 = base0 + NTILE;
#pragma unroll
        for (int p = 0; p < 16; p++) {
            base0[p] = f2_lo(acc[p][q]);
            base1[p] = f2_hi(acc[p][q]);
        }
    }
}

// ---------------- F(2,3) output transform: Y = A^T M A, + bias, relu ----------------
__global__ void __launch_bounds__(256) wino_out_kernel(const float* __restrict__ b_rpn) {
    const int t  = blockIdx.x * 256 + threadIdx.x;     // 0..2303
    const int oc = blockIdx.y;
    float m[16];
#pragma unroll
    for (int k = 0; k < 16; k++)
        m[k] = g_M[((size_t)k*512 + oc)*NTILE + t];

    float P0[4], P1[4];
#pragma unroll
    for (int j = 0; j < 4; j++) {
        P0[j] = m[j] + m[4+j] + m[8+j];
        P1[j] = m[4+j] - m[8+j] - m[12+j];
    }
    const float bias = b_rpn[oc];
    float y00 = P0[0] + P0[1] + P0[2] + bias;
    float y01 = P0[1] - P0[2] - P0[3] + bias;
    float y10 = P1[0] + P1[1] + P1[2] + bias;
    float y11 = P1[1] - P1[2] - P1[3] + bias;

    const int ty = t / 48, tx = t % 48;
    float* hp = g_h + (size_t)oc * NPIX + (2*ty)*96 + 2*tx;
    hp[0]    = y00 > 0.f ? y00 : 0.f;
    hp[1]    = y01 > 0.f ? y01 : 0.f;
    hp[96]   = y10 > 0.f ? y10 : 0.f;
    hp[97]   = y11 > 0.f ? y11 : 0.f;
}

// ---------------- 1x1 convs + decode, split-K over 4 ci-slices ----------------
// grid 144, block 256: 64 pixels x 4 slices of 128 ci. Slices 1-3 spill to smem,
// slice 0 reduces + decodes. Padded stride 57 -> conflict-free.
__global__ void __launch_bounds__(256) conv1x1_decode_kernel(
        const float* __restrict__ wcls, const float* __restrict__ bcls,
        const float* __restrict__ wreg, const float* __restrict__ breg,
        const float* __restrict__ anchors) {
    __shared__ float red[3][64][57];
    const int tid = threadIdx.x;
    const int p   = tid & 63;
    const int s   = tid >> 6;                 // 0..3
    const int pix = blockIdx.x * 64 + p;

    float acc[54];
#pragma unroll
    for (int o = 0; o < 54; o++) acc[o] = 0.f;

    const int cs = s * 128;
    for (int c = cs; c < cs + 128; c += 4) {
        float v0 = g_h[(size_t)(c+0)*NPIX + pix];
        float v1 = g_h[(size_t)(c+1)*NPIX + pix];
        float v2 = g_h[(size_t)(c+2)*NPIX + pix];
        float v3 = g_h[(size_t)(c+3)*NPIX + pix];
#pragma unroll
        for (int o = 0; o < 18; o++) {
            float4 w = *(const float4*)(wcls + o*512 + c);
            acc[o] += w.x*v0; acc[o] += w.y*v1; acc[o] += w.z*v2; acc[o] += w.w*v3;
        }
#pragma unroll
        for (int o = 0; o < 36; o++) {
            float4 w = *(const float4*)(wreg + o*512 + c);
            acc[18+o] += w.x*v0; acc[18+o] += w.y*v1; acc[18+o] += w.z*v2; acc[18+o] += w.w*v3;
        }
    }

    if (s > 0) {
#pragma unroll
        for (int o = 0; o < 54; o++) red[s-1][p][o] = acc[o];
    }
    __syncthreads();
    if (s != 0) return;

#pragma unroll
    for (int o = 0; o < 54; o++)
        acc[o] = ((acc[o] + red[0][p][o]) + red[1][p][o]) + red[2][p][o];

#pragma unroll
    for (int o = 0; o < 18; o++) g_cls[o*NPIX + pix] = acc[o] + bcls[o];

#pragma unroll
    for (int k = 0; k < 9; k++) {
        const int a = pix*9 + k;
        float c0 = acc[2*k    ] + bcls[2*k    ];
        float c1 = acc[2*k + 1] + bcls[2*k + 1];
        float r0 = acc[18 + 4*k + 0] + breg[4*k + 0];
        float r1 = acc[18 + 4*k + 1] + breg[4*k + 1];
        float r2 = acc[18 + 4*k + 2] + breg[4*k + 2];
        float r3 = acc[18 + 4*k + 3] + breg[4*k + 3];

        float4 an = ((const float4*)anchors)[a];
        float aw = an.z - an.x + 1.f;
        float ah = an.w - an.y + 1.f;
        float ax = an.x + 0.5f*(aw - 1.f);
        float ay = an.y + 0.5f*(ah - 1.f);
        float px = ax + aw * r0;
        float py = ay + ah * r1;
        float pw = aw * expf(r2);
        float ph = ah * expf(r3);
        float x0 = px - 0.5f*(pw - 1.f);
        float y0 = py - 0.5f*(ph - 1.f);
        float x1 = px + 0.5f*(pw - 1.f);
        float y1 = py + 0.5f*(ph - 1.f);

        ((float4*)g_prop)[a] = make_float4(x0, y0, x1, y1);
        float4 cb;
        cb.x = fminf(fmaxf(x0, 0.f), 1535.f);
        cb.y = fminf(fmaxf(y0, 0.f), 1535.f);
        cb.z = fminf(fmaxf(x1, 0.f), 1535.f);
        cb.w = fminf(fmaxf(y1, 0.f), 1535.f);
        ((float4*)g_bbox)[a] = cb;

        float m  = fmaxf(c0, c1);
        float e0 = expf(c0 - m);
        float e1 = expf(c1 - m);
        float prob = e1 / (e0 + e1);
        g_keys32[a] = ~__float_as_uint(prob);
        g_vals32[a] = a;
    }
}

// ---------------- fused greedy NMS (reads sorted keys/vals directly) ----------------
__global__ void __launch_bounds__(256) nms_fused_kernel(float* __restrict__ outF,
                                                        float* __restrict__ outP) {
    extern __shared__ float4 sb4[];                 // boxes[PRE_N]
    float* sarea = (float*)(sb4 + PRE_N);           // areas[PRE_N]
    __shared__ int kept[POS_N];
    __shared__ unsigned long long remv;
    __shared__ unsigned long long mw[64];
    __shared__ int kc;

    const int tid = threadIdx.x;
    for (int i = tid; i < PRE_N; i += 256) {
        int a = g_vals32_s[i];
        float4 b = ((const float4*)g_bbox)[a];
        sb4[i] = b;
        sarea[i] = (b.z - b.x + 1.f) * (b.w - b.y + 1.f);
    }
    if (tid == 0) kc = 0;
    __syncthreads();

    for (int g = 0; g < NWORDS; g++) {
        const int base = g * 64;
        const int lim  = min(64, PRE_N - base);
        if (tid == 0) remv = 0ull;
        if (tid < 64) mw[tid] = 0ull;
        __syncthreads();

        {
            const int c  = tid & 63;
            const int ks = tid >> 6;
            if (c < lim) {
                float4 bc = sb4[base + c];
                float  ac = sarea[base + c];
                bool sup = false;
                for (int t = ks; t < kc; t += 4) {
                    int i = kept[t];
                    float4 bi = sb4[i];
                    float iw = fminf(bi.z, bc.z) - fmaxf(bi.x, bc.x) + 1.f;
                    float ih = fminf(bi.w, bc.w) - fmaxf(bi.y, bc.y) + 1.f;
                    iw = fmaxf(iw, 0.f);
                    ih = fmaxf(ih, 0.f);
                    float inter = iw * ih;
                    float iou = inter / (sarea[i] + ac - inter);
                    if (iou > 0.7f) { sup = true; break; }
                }
                if (sup) atomicOr(&remv, 1ull << c);
            }
        }
        for (int e = tid; e < 64*64; e += 256) {
            const int r = e >> 6, c = e & 63;
            if (c > r && c < lim && r < lim) {
                float4 br = sb4[base + r];
                float4 bc = sb4[base + c];
                float iw = fminf(br.z, bc.z) - fmaxf(br.x, bc.x) + 1.f;
                float ih = fminf(br.w, bc.w) - fmaxf(br.y, bc.y) + 1.f;
                iw = fmaxf(iw, 0.f);
                ih = fmaxf(ih, 0.f);
                float inter = iw * ih;
                float iou = inter / (sarea[base + r] + sarea[base + c] - inter);
                if (iou > 0.7f) atomicOr(&mw[r], 1ull << c);
            }
        }
        __syncthreads();

        if (tid == 0) {
            unsigned long long limmask = (lim == 64) ? ~0ull : ((1ull << lim) - 1ull);
            unsigned long long avail = ~remv & limmask;
            int k = kc;
            while (avail && k < POS_N) {
                int b = __ffsll((long long)avail) - 1;
                kept[k++] = base + b;
                avail &= ~(mw[b] | (1ull << b));
            }
            kc = k;
        }
        __syncthreads();
        if (kc >= POS_N) break;
    }

    for (int rI = tid; rI < POS_N; rI += 256) {
        if (rI < kc) {
            int a = kept[rI];
            float4 b = sb4[a];
            outF[rI*4 + 0] = b.x;
            outF[rI*4 + 1] = b.y;
            outF[rI*4 + 2] = b.z;
            outF[rI*4 + 3] = b.w;
            outP[rI] = __uint_as_float(~g_keys32_s[a]);
        } else {
            outF[rI*4 + 0] = 0.f; outF[rI*4 + 1] = 0.f;
            outF[rI*4 + 2] = 0.f; outF[rI*4 + 3] = 0.f;
            outP[rI] = 0.f;
        }
    }
}

// ---------------- gather proposals[valid_idx], cls[valid_idx] ----------------
__global__ void gather_valid_kernel(const int* __restrict__ vidx, int nv,
                                    float* __restrict__ out) {
    int i = blockIdx.x * 256 + threadIdx.x;
    if (i >= nv) return;
    int a = vidx[i];
    out[i*4 + 0] = g_prop[a*4 + 0];
    out[i*4 + 1] = g_prop[a*4 + 1];
    out[i*4 + 2] = g_prop[a*4 + 2];
    out[i*4 + 3] = g_prop[a*4 + 3];
    int pix = a / 9, k = a % 9;
    out[(long long)nv*4 + i*2 + 0] = g_cls[(k*2 + 0)*NPIX + pix];
    out[(long long)nv*4 + i*2 + 1] = g_cls[(k*2 + 1)*NPIX + pix];
}

// ---------------- host ----------------
extern "C" void kernel_launch(void* const* d_in, const int* in_sizes, int n_in,
                              void* d_out, int out_size) {
    int ix=-1, iwr=-1, ibr=-1, iwc=-1, ibc=-1, iwg=-1, ibg=-1, ian=-1, ivi=-1;
    int nv = (out_size - (POS_N*4 + POS_N)) / 6;
    for (int i = 0; i < n_in; i++) {
        int s = in_sizes[i];
        if      (s == 1024*NPIX)     ix  = i;
        else if (s == 512*1024*9)    iwr = i;
        else if (s == 512)           ibr = i;
        else if (s == 18*512)        iwc = i;
        else if (s == 18)            ibc = i;
        else if (s == 36*512)        iwg = i;
        else if (s == 36)            ibg = i;
        else if (s == NANCH*4)       ian = i;
        else if (s == nv)            ivi = i;
    }
    if (ivi < 0) ivi = 8;

    const float* x      = (const float*)d_in[ix];
    const float* w_rpn  = (const float*)d_in[iwr];
    const float* b_rpn  = (const float*)d_in[ibr];
    const float* w_cls  = (const float*)d_in[iwc];
    const float* b_cls  = (const float*)d_in[ibc];
    const float* w_reg  = (const float*)d_in[iwg];
    const float* b_reg  = (const float*)d_in[ibg];
    const float* anch   = (const float*)d_in[ian];
    const int*   vidx   = (const int*)d_in[ivi];
    float* out = (float*)d_out;

    const int NMS_SMEM = PRE_N * (int)sizeof(float4) + PRE_N * (int)sizeof(float); // 120000
    cudaFuncSetAttribute(nms_fused_kernel,
                         cudaFuncAttributeMaxDynamicSharedMemorySize, NMS_SMEM);

    prep_kernel<<<9216 + 2048, 256>>>(x, w_rpn);
    wino_gemm_kernel<<<dim3(18, 2, 16), 256>>>();
    wino_out_kernel<<<dim3(9, 512), 256>>>(b_rpn);
    conv1x1_decode_kernel<<<144, 256>>>(w_cls, b_cls, w_reg, b_reg, anch);

    void *d_temp, *d_kin, *d_kout, *d_vin, *d_vout;
    cudaGetSymbolAddress(&d_temp, g_cub_temp);
    cudaGetSymbolAddress(&d_kin,  g_keys32);
    cudaGetSymbolAddress(&d_kout, g_keys32_s);
    cudaGetSymbolAddress(&d_vin,  g_vals32);
    cudaGetSymbolAddress(&d_vout, g_vals32_s);
    size_t temp_bytes = sizeof(g_cub_temp);
    cub::DeviceRadixSort::SortPairs(d_temp, temp_bytes,
                                    (const unsigned*)d_kin, (unsigned*)d_kout,
                                    (const int*)d_vin, (int*)d_vout,
                                    NANCH, 0, 32, (cudaStream_t)0);

    nms_fused_kernel<<<1, 256, NMS_SMEM>>>(out + (long long)nv*6,
                                           out + (long long)nv*6 + POS_N*4);
    gather_valid_kernel<<<(nv + 255)/256, 256>>>(vidx, nv, out);
}

// round 16
// speedup vs baseline: 1.1450x; 1.0066x over previous
#include <cuda_runtime.h>
#include <cub/cub.cuh>

#define NPIX   9216     // 96*96
#define NANCH  82944    // NPIX*9
#define PRE_N  6000
#define POS_N  300
#define NWORDS 94       // ceil(6000/64)
#define NTILE  2304     // 48*48 winograd 2x2 tiles

// ---------------- scratch (static device memory; no allocation) ----------------
__device__ float g_V[16*1024*NTILE];        // winograd input  [k16][ci][tile]
__device__ float g_U[16*1024*512];          // winograd weight [k16][ci][oc]
__device__ float g_M[16*512*NTILE];         // winograd product [k16][oc][tile]
__device__ float g_h[512*NPIX];             // relu(conv3x3) output [oc][pix]
__device__ float g_cls[18*NPIX];            // cls logits [ch][pix] (for gather_valid)
__device__ float g_prop[NANCH*4];           // unclipped proposals
__device__ float g_bbox[NANCH*4];           // clipped boxes
__device__ unsigned g_keys32[NANCH];
__device__ int      g_vals32[NANCH];
__device__ unsigned g_keys32_s[NANCH];
__device__ int      g_vals32_s[NANCH];
__device__ unsigned char g_cub_temp[8<<20];

// ---------------- packed f32x2 helpers ----------------
__device__ __forceinline__ void ffma2(unsigned long long &d,
                                      unsigned long long a,
                                      unsigned long long b) {
    asm("fma.rn.f32x2 %0, %1, %2, %0;" : "+l"(d) : "l"(a), "l"(b));
}
__device__ __forceinline__ float f2_lo(unsigned long long v) {
    return __uint_as_float((unsigned)(v & 0xffffffffull));
}
__device__ __forceinline__ float f2_hi(unsigned long long v) {
    return __uint_as_float((unsigned)(v >> 32));
}

// ---------------- merged prep: input transform (blocks 0..9215) + weight transform ----------------
__global__ void __launch_bounds__(256) prep_kernel(const float* __restrict__ x,
                                                   const float* __restrict__ wsrc) {
    if (blockIdx.x < 9216) {
        const int ci = blockIdx.x / 9;
        const int t  = (blockIdx.x % 9) * 256 + threadIdx.x;   // 0..2303
        const int ty = t / 48, tx = t % 48;
        const int r0 = 2*ty - 1, c0 = 2*tx - 1;
        const float* xp = x + (size_t)ci * NPIX;

        float d[4][4];
#pragma unroll
        for (int a = 0; a < 4; a++) {
            const int rr = r0 + a;
            const bool rok = (unsigned)rr < 96u;
#pragma unroll
            for (int b = 0; b < 4; b++) {
                const int cc = c0 + b;
                d[a][b] = (rok && (unsigned)cc < 96u) ? xp[rr*96 + cc] : 0.f;
            }
        }
        float w[4][4];
#pragma unroll
        for (int j = 0; j < 4; j++) {
            w[0][j] = d[0][j] - d[2][j];
            w[1][j] = d[1][j] + d[2][j];
            w[2][j] = d[2][j] - d[1][j];
            w[3][j] = d[1][j] - d[3][j];
        }
#pragma unroll
        for (int i = 0; i < 4; i++) {
            float v0 = w[i][0] - w[i][2];
            float v1 = w[i][1] + w[i][2];
            float v2 = w[i][2] - w[i][1];
            float v3 = w[i][1] - w[i][3];
            g_V[((size_t)(i*4+0)*1024 + ci)*NTILE + t] = v0;
            g_V[((size_t)(i*4+1)*1024 + ci)*NTILE + t] = v1;
            g_V[((size_t)(i*4+2)*1024 + ci)*NTILE + t] = v2;
            g_V[((size_t)(i*4+3)*1024 + ci)*NTILE + t] = v3;
        }
    } else {
        const int idx = (blockIdx.x - 9216) * 256 + threadIdx.x;   // 512*1024
        const int oc = idx & 511;
        const int ci = idx >> 9;
        float g[9];
#pragma unroll
        for (int j = 0; j < 9; j++) g[j] = wsrc[((size_t)oc*1024 + ci)*9 + j];

        float T[4][3];
#pragma unroll
        for (int j = 0; j < 3; j++) {
            T[0][j] = g[j];
            T[1][j] = 0.5f*(g[j] + g[3+j] + g[6+j]);
            T[2][j] = 0.5f*(g[j] - g[3+j] + g[6+j]);
            T[3][j] = g[6+j];
        }
#pragma unroll
        for (int i = 0; i < 4; i++) {
            float u0 = T[i][0];
            float u1 = 0.5f*(T[i][0] + T[i][1] + T[i][2]);
            float u2 = 0.5f*(T[i][0] - T[i][1] + T[i][2]);
            float u3 = T[i][2];
            g_U[((size_t)(i*4+0)*1024 + ci)*512 + oc] = u0;
            g_U[((size_t)(i*4+1)*1024 + ci)*512 + oc] = u1;
            g_U[((size_t)(i*4+2)*1024 + ci)*512 + oc] = u2;
            g_U[((size_t)(i*4+3)*1024 + ci)*512 + oc] = u3;
        }
    }
}

// ---------------- winograd GEMM, k8 blocks, XOR-swizzled A, LDS.128 reads ----------------
__global__ void __launch_bounds__(256, 1) wino_gemm_kernel() {
    __shared__ float2 xa[2][8][128];
    __shared__ float  wb[2][8][256];

    const int tid = threadIdx.x;
    const int og  = tid >> 3;        // 0..31
    const int pg  = tid & 7;         // 0..7 -> 16 m each
    const int m0  = blockIdx.x * 128;
    const int ocb = blockIdx.y * 256;
    const int z   = blockIdx.z;

    const float* Ag = g_V + (size_t)z * 1024 * NTILE;
    const float* Bg = g_U + (size_t)z * 1024 * 512;

    unsigned long long acc[16][4];
#pragma unroll
    for (int p = 0; p < 16; p++)
#pragma unroll
        for (int q = 0; q < 4; q++) acc[p][q] = 0ull;

    float av[4], bv[8];
    int aphys[4];
#pragma unroll
    for (int i = 0; i < 4; i++) {
        const int idx = i*256 + tid;
        const int mel = idx & 127;
        aphys[i] = (idx >> 7) * 128 + (mel & 0x70) + ((mel & 15) ^ ((mel >> 3) & 14));
    }

#pragma unroll
    for (int i = 0; i < 4; i++) {
        int idx = i*256 + tid;
        av[i] = Ag[(size_t)(idx >> 7) * NTILE + m0 + (idx & 127)];
    }
#pragma unroll
    for (int i = 0; i < 8; i++) bv[i] = Bg[(size_t)i * 512 + ocb + tid];
#pragma unroll
    for (int i = 0; i < 4; i++)
        (&xa[0][0][0])[aphys[i]] = make_float2(av[i], av[i]);
#pragma unroll
    for (int i = 0; i < 8; i++) wb[0][i][tid] = bv[i];

    const int sw = pg * 2;   // reader XOR swizzle (even)

    for (int it = 0; it < 128; it++) {
        const int b = it & 1;
        if (it < 127) {
            const int k0 = (it + 1) * 8;
#pragma unroll
            for (int i = 0; i < 4; i++) {
                int idx = i*256 + tid;
                av[i] = Ag[(size_t)(k0 + (idx >> 7)) * NTILE + m0 + (idx & 127)];
            }
#pragma unroll
            for (int i = 0; i < 8; i++) bv[i] = Bg[(size_t)(k0 + i) * 512 + ocb + tid];
        }
        __syncthreads();    // buffer b staged

#pragma unroll
        for (int kk = 0; kk < 8; kk++) {
            unsigned long long xr[16];
#pragma unroll
            for (int j = 0; j < 8; j++) {
                const float2* src = &xa[b][kk][pg*16 + ((2*j) ^ sw)];
                float4 v = *(const float4*)src;
                xr[2*j]   = *(unsigned long long*)&v.x;
                xr[2*j+1] = *(unsigned long long*)&v.z;
            }
            const unsigned long long* wp =
                (const unsigned long long*)&wb[b][kk][og*8];
            const unsigned long long w0 = wp[0], w1 = wp[1], w2 = wp[2], w3 = wp[3];
#pragma unroll
            for (int p = 0; p < 16; p++) {
                ffma2(acc[p][0], w0, xr[p]);
                ffma2(acc[p][1], w1, xr[p]);
                ffma2(acc[p][2], w2, xr[p]);
                ffma2(acc[p][3], w3, xr[p]);
            }
        }

        if (it < 127) {
            __syncthreads();
            const int nb = b ^ 1;
#pragma unroll
            for (int i = 0; i < 4; i++)
                (&xa[nb][0][0])[aphys[i]] = make_float2(av[i], av[i]);
#pragma unroll
            for (int i = 0; i < 8; i++) wb[nb][i][tid] = bv[i];
        }
    }

#pragma unroll
    for (int q = 0; q < 4; q++) {
        const int oc0 = ocb + og*8 + 2*q;
        float* base0 = g_M + ((size_t)z*512 + oc0) * NTILE + m0 + pg*16;
        float* base1 = base0 + NTILE;
#pragma unroll
        for (int p = 0; p < 16; p++) {
            base0[p] = f2_lo(acc[p][q]);
            base1[p] = f2_hi(acc[p][q]);
        }
    }
}

// ---------------- F(2,3) output transform: Y = A^T M A, + bias, relu ----------------
__global__ void __launch_bounds__(256) wino_out_kernel(const float* __restrict__ b_rpn) {
    const int t  = blockIdx.x * 256 + threadIdx.x;     // 0..2303
    const int oc = blockIdx.y;
    float m[16];
#pragma unroll
    for (int k = 0; k < 16; k++)
        m[k] = g_M[((size_t)k*512 + oc)*NTILE + t];

    float P0[4], P1[4];
#pragma unroll
    for (int j = 0; j < 4; j++) {
        P0[j] = m[j] + m[4+j] + m[8+j];
        P1[j] = m[4+j] - m[8+j] - m[12+j];
    }
    const float bias = b_rpn[oc];
    float y00 = P0[0] + P0[1] + P0[2] + bias;
    float y01 = P0[1] - P0[2] - P0[3] + bias;
    float y10 = P1[0] + P1[1] + P1[2] + bias;
    float y11 = P1[1] - P1[2] - P1[3] + bias;

    const int ty = t / 48, tx = t % 48;
    float* hp = g_h + (size_t)oc * NPIX + (2*ty)*96 + 2*tx;
    hp[0]    = y00 > 0.f ? y00 : 0.f;
    hp[1]    = y01 > 0.f ? y01 : 0.f;
    hp[96]   = y10 > 0.f ? y10 : 0.f;
    hp[97]   = y11 > 0.f ? y11 : 0.f;
}

// ---------------- 1x1 convs + decode, split-K over 8 ci-slices, block 512 ----------------
// grid 144, block 512: 64 pixels x 8 slices of 64 ci. Slices 1-7 spill to dynamic smem
// (padded stride 57 -> conflict-free), slice 0 reduces + decodes.
__global__ void __launch_bounds__(512, 1) conv1x1_decode_kernel(
        const float* __restrict__ wcls, const float* __restrict__ bcls,
        const float* __restrict__ wreg, const float* __restrict__ breg,
        const float* __restrict__ anchors) {
    extern __shared__ float red[];            // [7][64][57]
    const int tid = threadIdx.x;
    const int p   = tid & 63;
    const int s   = tid >> 6;                 // 0..7
    const int pix = blockIdx.x * 64 + p;

    float acc[54];
#pragma unroll
    for (int o = 0; o < 54; o++) acc[o] = 0.f;

    const int cs = s * 64;
    for (int c = cs; c < cs + 64; c += 4) {
        float v0 = g_h[(size_t)(c+0)*NPIX + pix];
        float v1 = g_h[(size_t)(c+1)*NPIX + pix];
        float v2 = g_h[(size_t)(c+2)*NPIX + pix];
        float v3 = g_h[(size_t)(c+3)*NPIX + pix];
#pragma unroll
        for (int o = 0; o < 18; o++) {
            float4 w = *(const float4*)(wcls + o*512 + c);
            acc[o] += w.x*v0; acc[o] += w.y*v1; acc[o] += w.z*v2; acc[o] += w.w*v3;
        }
#pragma unroll
        for (int o = 0; o < 36; o++) {
            float4 w = *(const float4*)(wreg + o*512 + c);
            acc[18+o] += w.x*v0; acc[18+o] += w.y*v1; acc[18+o] += w.z*v2; acc[18+o] += w.w*v3;
        }
    }

    if (s > 0) {
#pragma unroll
        for (int o = 0; o < 54; o++) red[((s-1)*64 + p)*57 + o] = acc[o];
    }
    __syncthreads();
    if (s != 0) return;

#pragma unroll
    for (int j = 0; j < 7; j++)
#pragma unroll
        for (int o = 0; o < 54; o++)
            acc[o] += red[(j*64 + p)*57 + o];

#pragma unroll
    for (int o = 0; o < 18; o++) g_cls[o*NPIX + pix] = acc[o] + bcls[o];

#pragma unroll
    for (int k = 0; k < 9; k++) {
        const int a = pix*9 + k;
        float c0 = acc[2*k    ] + bcls[2*k    ];
        float c1 = acc[2*k + 1] + bcls[2*k + 1];
        float r0 = acc[18 + 4*k + 0] + breg[4*k + 0];
        float r1 = acc[18 + 4*k + 1] + breg[4*k + 1];
        float r2 = acc[18 + 4*k + 2] + breg[4*k + 2];
        float r3 = acc[18 + 4*k + 3] + breg[4*k + 3];

        float4 an = ((const float4*)anchors)[a];
        float aw = an.z - an.x + 1.f;
        float ah = an.w - an.y + 1.f;
        float ax = an.x + 0.5f*(aw - 1.f);
        float ay = an.y + 0.5f*(ah - 1.f);
        float px = ax + aw * r0;
        float py = ay + ah * r1;
        float pw = aw * expf(r2);
        float ph = ah * expf(r3);
        float x0 = px - 0.5f*(pw - 1.f);
        float y0 = py - 0.5f*(ph - 1.f);
        float x1 = px + 0.5f*(pw - 1.f);
        float y1 = py + 0.5f*(ph - 1.f);

        ((float4*)g_prop)[a] = make_float4(x0, y0, x1, y1);
        float4 cb;
        cb.x = fminf(fmaxf(x0, 0.f), 1535.f);
        cb.y = fminf(fmaxf(y0, 0.f), 1535.f);
        cb.z = fminf(fmaxf(x1, 0.f), 1535.f);
        cb.w = fminf(fmaxf(y1, 0.f), 1535.f);
        ((float4*)g_bbox)[a] = cb;

        float m  = fmaxf(c0, c1);
        float e0 = expf(c0 - m);
        float e1 = expf(c1 - m);
        float prob = e1 / (e0 + e1);
        g_keys32[a] = ~__float_as_uint(prob);
        g_vals32[a] = a;
    }
}

// ---------------- fused greedy NMS (reads sorted keys/vals directly) ----------------
__global__ void __launch_bounds__(256) nms_fused_kernel(float* __restrict__ outF,
                                                        float* __restrict__ outP) {
    extern __shared__ float4 sb4[];                 // boxes[PRE_N]
    float* sarea = (float*)(sb4 + PRE_N);           // areas[PRE_N]
    __shared__ int kept[POS_N];
    __shared__ unsigned long long remv;
    __shared__ unsigned long long mw[64];
    __shared__ int kc;

    const int tid = threadIdx.x;
    for (int i = tid; i < PRE_N; i += 256) {
        int a = g_vals32_s[i];
        float4 b = ((const float4*)g_bbox)[a];
        sb4[i] = b;
        sarea[i] = (b.z - b.x + 1.f) * (b.w - b.y + 1.f);
    }
    if (tid == 0) kc = 0;
    __syncthreads();

    for (int g = 0; g < NWORDS; g++) {
        const int base = g * 64;
        const int lim  = min(64, PRE_N - base);
        if (tid == 0) remv = 0ull;
        if (tid < 64) mw[tid] = 0ull;
        __syncthreads();

        {
            const int c  = tid & 63;
            const int ks = tid >> 6;
            if (c < lim) {
                float4 bc = sb4[base + c];
                float  ac = sarea[base + c];
                bool sup = false;
                for (int t = ks; t < kc; t += 4) {
                    int i = kept[t];
                    float4 bi = sb4[i];
                    float iw = fminf(bi.z, bc.z) - fmaxf(bi.x, bc.x) + 1.f;
                    float ih = fminf(bi.w, bc.w) - fmaxf(bi.y, bc.y) + 1.f;
                    iw = fmaxf(iw, 0.f);
                    ih = fmaxf(ih, 0.f);
                    float inter = iw * ih;
                    float iou = inter / (sarea[i] + ac - inter);
                    if (iou > 0.7f) { sup = true; break; }
                }
                if (sup) atomicOr(&remv, 1ull << c);
            }
        }
        for (int e = tid; e < 64*64; e += 256) {
            const int r = e >> 6, c = e & 63;
            if (c > r && c < lim && r < lim) {
                float4 br = sb4[base + r];
                float4 bc = sb4[base + c];
                float iw = fminf(br.z, bc.z) - fmaxf(br.x, bc.x) + 1.f;
                float ih = fminf(br.w, bc.w) - fmaxf(br.y, bc.y) + 1.f;
                iw = fmaxf(iw, 0.f);
                ih = fmaxf(ih, 0.f);
                float inter = iw * ih;
                float iou = inter / (sarea[base + r] + sarea[base + c] - inter);
                if (iou > 0.7f) atomicOr(&mw[r], 1ull << c);
            }
        }
        __syncthreads();

        if (tid == 0) {
            unsigned long long limmask = (lim == 64) ? ~0ull : ((1ull << lim) - 1ull);
            unsigned long long avail = ~remv & limmask;
            int k = kc;
            while (avail && k < POS_N) {
                int b = __ffsll((long long)avail) - 1;
                kept[k++] = base + b;
                avail &= ~(mw[b] | (1ull << b));
            }
            kc = k;
        }
        __syncthreads();
        if (kc >= POS_N) break;
    }

    for (int rI = tid; rI < POS_N; rI += 256) {
        if (rI < kc) {
            int a = kept[rI];
            float4 b = sb4[a];
            outF[rI*4 + 0] = b.x;
            outF[rI*4 + 1] = b.y;
            outF[rI*4 + 2] = b.z;
            outF[rI*4 + 3] = b.w;
            outP[rI] = __uint_as_float(~g_keys32_s[a]);
        } else {
            outF[rI*4 + 0] = 0.f; outF[rI*4 + 1] = 0.f;
            outF[rI*4 + 2] = 0.f; outF[rI*4 + 3] = 0.f;
            outP[rI] = 0.f;
        }
    }
}

// ---------------- gather proposals[valid_idx], cls[valid_idx] ----------------
__global__ void gather_valid_kernel(const int* __restrict__ vidx, int nv,
                                    float* __restrict__ out) {
    int i = blockIdx.x * 256 + threadIdx.x;
    if (i >= nv) return;
    int a = vidx[i];
    out[i*4 + 0] = g_prop[a*4 + 0];
    out[i*4 + 1] = g_prop[a*4 + 1];
    out[i*4 + 2] = g_prop[a*4 + 2];
    out[i*4 + 3] = g_prop[a*4 + 3];
    int pix = a / 9, k = a % 9;
    out[(long long)nv*4 + i*2 + 0] = g_cls[(k*2 + 0)*NPIX + pix];
    out[(long long)nv*4 + i*2 + 1] = g_cls[(k*2 + 1)*NPIX + pix];
}

// ---------------- host ----------------
extern "C" void kernel_launch(void* const* d_in, const int* in_sizes, int n_in,
                              void* d_out, int out_size) {
    int ix=-1, iwr=-1, ibr=-1, iwc=-1, ibc=-1, iwg=-1, ibg=-1, ian=-1, ivi=-1;
    int nv = (out_size - (POS_N*4 + POS_N)) / 6;
    for (int i = 0; i < n_in; i++) {
        int s = in_sizes[i];
        if      (s == 1024*NPIX)     ix  = i;
        else if (s == 512*1024*9)    iwr = i;
        else if (s == 512)           ibr = i;
        else if (s == 18*512)        iwc = i;
        else if (s == 18)            ibc = i;
        else if (s == 36*512)        iwg = i;
        else if (s == 36)            ibg = i;
        else if (s == NANCH*4)       ian = i;
        else if (s == nv)            ivi = i;
    }
    if (ivi < 0) ivi = 8;

    const float* x      = (const float*)d_in[ix];
    const float* w_rpn  = (const float*)d_in[iwr];
    const float* b_rpn  = (const float*)d_in[ibr];
    const float* w_cls  = (const float*)d_in[iwc];
    const float* b_cls  = (const float*)d_in[ibc];
    const float* w_reg  = (const float*)d_in[iwg];
    const float* b_reg  = (const float*)d_in[ibg];
    const float* anch   = (const float*)d_in[ian];
    const int*   vidx   = (const int*)d_in[ivi];
    float* out = (float*)d_out;

    const int NMS_SMEM = PRE_N * (int)sizeof(float4) + PRE_N * (int)sizeof(float); // 120000
    cudaFuncSetAttribute(nms_fused_kernel,
                         cudaFuncAttributeMaxDynamicSharedMemorySize, NMS_SMEM);
    const int C1_SMEM = 7 * 64 * 57 * (int)sizeof(float);                          // 102144
    cudaFuncSetAttribute(conv1x1_decode_kernel,
                         cudaFuncAttributeMaxDynamicSharedMemorySize, C1_SMEM);

    prep_kernel<<<9216 + 2048, 256>>>(x, w_rpn);
    wino_gemm_kernel<<<dim3(18, 2, 16), 256>>>();
    wino_out_kernel<<<dim3(9, 512), 256>>>(b_rpn);
    conv1x1_decode_kernel<<<144, 512, C1_SMEM>>>(w_cls, b_cls, w_reg, b_reg, anch);

    void *d_temp, *d_kin, *d_kout, *d_vin, *d_vout;
    cudaGetSymbolAddress(&d_temp, g_cub_temp);
    cudaGetSymbolAddress(&d_kin,  g_keys32);
    cudaGetSymbolAddress(&d_kout, g_keys32_s);
    cudaGetSymbolAddress(&d_vin,  g_vals32);
    cudaGetSymbolAddress(&d_vout, g_vals32_s);
    size_t temp_bytes = sizeof(g_cub_temp);
    cub::DeviceRadixSort::SortPairs(d_temp, temp_bytes,
                                    (const unsigned*)d_kin, (unsigned*)d_kout,
                                    (const int*)d_vin, (int*)d_vout,
                                    NANCH, 0, 32, (cudaStream_t)0);

    nms_fused_kernel<<<1, 256, NMS_SMEM>>>(out + (long long)nv*6,
                                           out + (long long)nv*6 + POS_N*4);
    gather_valid_kernel<<<(nv + 255)/256, 256>>>(vidx, nv, out);
}